// round 10
// baseline (speedup 1.0000x reference)
#include <cuda_runtime.h>
#include <cuda_bf16.h>
#include <cstdint>
#include <math.h>

#define BL 512
#define DIM 512
#define NROWS 32768
#define NBLK 64

// Scratch (allocation-free rule: __device__ globals)
__device__ __nv_bfloat16 g_Xh [(size_t)NROWS*DIM];
__device__ __nv_bfloat16 g_Wth[(size_t)3*DIM*DIM];
__device__ __nv_bfloat16 g_Qh [(size_t)NROWS*DIM];
__device__ __nv_bfloat16 g_Kh [(size_t)NROWS*DIM];
__device__ __nv_bfloat16 g_Vh [(size_t)NROWS*DIM];
__device__ __nv_bfloat16 g_Ph [(size_t)NBLK*BL*BL];   // unnormalized exp(S), bf16

// ---------------------------------------------------------------------------
__device__ __forceinline__ uint32_t smem_u32(const void* p) {
    uint32_t a;
    asm("{ .reg .u64 t; cvta.to.shared.u64 t, %1; cvt.u32.u64 %0, t; }" : "=r"(a) : "l"(p));
    return a;
}
#define CP16(dst, src) \
    asm volatile("cp.async.cg.shared.global [%0], [%1], 16;" :: "r"(dst), "l"(src))
#define CPCOMMIT() asm volatile("cp.async.commit_group;" ::: "memory")
#define CPWAIT3()  asm volatile("cp.async.wait_group 3;" ::: "memory")
#define CPWAIT0()  asm volatile("cp.async.wait_group 0;" ::: "memory")
#define LDSM4(R, addr) \
    asm volatile("ldmatrix.sync.aligned.m8n8.x4.shared.b16 {%0,%1,%2,%3}, [%4];" \
        : "=r"((R)[0]), "=r"((R)[1]), "=r"((R)[2]), "=r"((R)[3]) : "r"(addr))
#define LDSM4T(R, addr) \
    asm volatile("ldmatrix.sync.aligned.m8n8.x4.trans.shared.b16 {%0,%1,%2,%3}, [%4];" \
        : "=r"((R)[0]), "=r"((R)[1]), "=r"((R)[2]), "=r"((R)[3]) : "r"(addr))

__device__ __forceinline__ void mma16(float* c, const uint32_t* a, const uint32_t* b) {
    asm volatile(
        "mma.sync.aligned.m16n8k16.row.col.f32.bf16.bf16.f32 "
        "{%0,%1,%2,%3},{%4,%5,%6,%7},{%8,%9},{%0,%1,%2,%3};"
        : "+f"(c[0]), "+f"(c[1]), "+f"(c[2]), "+f"(c[3])
        : "r"(a[0]), "r"(a[1]), "r"(a[2]), "r"(a[3]),
          "r"(b[0]), "r"(b[1]));
}
__device__ __forceinline__ float bf2sum(uint32_t u) {
    __nv_bfloat162 h = *(__nv_bfloat162*)&u;
    float2 f = __bfloat1622float2(h);
    return f.x + f.y;
}

// ---------------------------------------------------------------------------
// BK=32 pipeline: A/B(NT) stages 128 rows x 80 B; V(NN trans) stage 32 rows
// x 272 B. 5 stages, prefetch depth 4 (wait_group 3, empty-commit tail).
// ---------------------------------------------------------------------------
#define AROW_B      80                 /* 64 B data + 16 pad */
#define VROW_B      272                /* 256 B data + 16 pad */
#define A_STG       (128*AROW_B)       /* 10240 */
#define V_STG       (32*VROW_B)        /* 8704 */
#define NSTAGE      5
#define NCHUNK      16
#define SMEM_BYTES  (2*NSTAGE*A_STG)   /* 102400 -> 2 CTAs/SM */
#define B_OFF       (NSTAGE*A_STG)

#define ACC_INIT(acc)                                         \
    float acc[2][8][4];                                       \
    _Pragma("unroll") for (int i = 0; i < 2; i++)             \
    _Pragma("unroll") for (int j = 0; j < 8; j++)             \
    _Pragma("unroll") for (int k = 0; k < 4; k++) acc[i][j][k] = 0.f;

// ---------------------------------------------------------------------------
// NT mainloop (both operands K-major): acc = A[128x512] @ B[128x512]^T
// ---------------------------------------------------------------------------
__device__ __forceinline__ void bf16_gemm_128x128(
    const __nv_bfloat16* __restrict__ A, const __nv_bfloat16* __restrict__ B,
    uint32_t sb, int tid, float acc[2][8][4])
{
    const int lane = tid & 31, wid = tid >> 5;
    const int wm = wid & 3, wn = wid >> 2;
    const int a_row = wm * 32 + (lane & 15);
    const int a_kb  = (lane >> 4) * 16;
    const int b_row = wn * 64 + ((lane >> 4) << 3) + (lane & 7);
    const int b_kb  = ((lane >> 3) & 1) * 16;
    const uint32_t a_base = sb + (uint32_t)(a_row * AROW_B) + a_kb;
    const uint32_t b_base = sb + B_OFF + (uint32_t)(b_row * AROW_B) + b_kb;

    // load K-chunk c (32 bf16/row) into stage s: 2 CP16 per thread per operand
    auto load = [&](int c, int s) {
        const uint32_t as = sb + (uint32_t)s * A_STG;
        const uint32_t bs = sb + B_OFF + (uint32_t)s * A_STG;
#pragma unroll
        for (int t = 0; t < 2; t++) {
            int idx = tid + t * 256;
            int r = idx >> 2, c4 = idx & 3;
            uint32_t doff = (uint32_t)(r * AROW_B + c4 * 16);
            CP16(as + doff, A + (size_t)r * DIM + c * 32 + c4 * 8);
            CP16(bs + doff, B + (size_t)r * DIM + c * 32 + c4 * 8);
        }
        CPCOMMIT();
    };

    load(0, 0); load(1, 1); load(2, 2); load(3, 3);
#pragma unroll 1
    for (int c = 0; c < NCHUNK; c++) {
        CPWAIT3();
        __syncthreads();
        if (c + 4 < NCHUNK) load(c + 4, (c + 4) % NSTAGE); else CPCOMMIT();
        const int s = c % NSTAGE;
        const uint32_t aaddr = a_base + (uint32_t)s * A_STG;
        const uint32_t baddr = b_base + (uint32_t)s * A_STG;
#pragma unroll
        for (int ks = 0; ks < 2; ks++) {
            uint32_t af[2][4], bf[4][4];
            LDSM4(af[0], aaddr + ks * 32);
            LDSM4(af[1], aaddr + ks * 32 + 16 * AROW_B);
#pragma unroll
            for (int gg = 0; gg < 4; gg++)
                LDSM4(bf[gg], baddr + ks * 32 + gg * 16 * AROW_B);
#pragma unroll
            for (int mt = 0; mt < 2; mt++)
#pragma unroll
                for (int gg = 0; gg < 4; gg++) {
                    mma16(acc[mt][2 * gg + 0], af[mt], &bf[gg][0]);
                    mma16(acc[mt][2 * gg + 1], af[mt], &bf[gg][2]);
                }
        }
    }
    CPWAIT0();
}

// ---------------------------------------------------------------------------
// QKV: grid (4, 256, 3). C bf16 = X@Wt^T + bias
// ---------------------------------------------------------------------------
__global__ void __launch_bounds__(256, 2)
tc_gemm_qkv(const __nv_bfloat16* __restrict__ Xh, const __nv_bfloat16* __restrict__ Wth,
            const float* __restrict__ b0, const float* __restrict__ b1,
            const float* __restrict__ b2,
            __nv_bfloat16* __restrict__ Qh, __nv_bfloat16* __restrict__ Kh,
            __nv_bfloat16* __restrict__ Vh)
{
    extern __shared__ uint32_t smu[];
    const uint32_t sb = smem_u32(smu);
    const int tid = threadIdx.x;
    const int z = blockIdx.z;
    const int bm = blockIdx.y * 128, bn = blockIdx.x * 128;

    const __nv_bfloat16* A = Xh + (size_t)bm * DIM;
    const __nv_bfloat16* B = Wth + (size_t)z * DIM * DIM + (size_t)bn * DIM;
    const float* bias = (z == 0) ? b0 : (z == 1) ? b1 : b2;
    __nv_bfloat16* C = (z == 0) ? Qh : (z == 1) ? Kh : Vh;

    ACC_INIT(acc);
    bf16_gemm_128x128(A, B, sb, tid, acc);

    const int lane = tid & 31, wid = tid >> 5;
    const int wm = wid & 3, wn = wid >> 2;
    const int q = lane & 3, rg = lane >> 2;
#pragma unroll
    for (int mt = 0; mt < 2; mt++)
#pragma unroll
    for (int nt = 0; nt < 8; nt++) {
        const int rl0 = bm + wm * 32 + mt * 16 + rg;
        const int cl  = bn + wn * 64 + nt * 8 + 2 * q;
        float2 bv = *(const float2*)(bias + cl);
#pragma unroll
        for (int h = 0; h < 2; h++) {
            const int r = rl0 + h * 8;
            float v0 = acc[mt][nt][2 * h + 0] + bv.x;
            float v1 = acc[mt][nt][2 * h + 1] + bv.y;
            __nv_bfloat162 o = __float22bfloat162_rn(make_float2(v0, v1));
            *(__nv_bfloat162*)(C + (size_t)r * DIM + cl) = o;
        }
    }
}

// ---------------------------------------------------------------------------
// Scores+exp: P bf16 = exp(scale*(Q@K^T) + (1-mask)*(-1e10))  [no-max softmax]
// grid (4, 4, 64)
// ---------------------------------------------------------------------------
__global__ void __launch_bounds__(256, 2)
tc_gemm_scores(const __nv_bfloat16* __restrict__ Qg, const __nv_bfloat16* __restrict__ Kg,
               const float* __restrict__ mask, __nv_bfloat16* __restrict__ Pg)
{
    extern __shared__ uint32_t smu[];
    const uint32_t sb = smem_u32(smu);
    const int tid = threadIdx.x;
    const size_t zoff = (size_t)blockIdx.z * (BL * DIM);
    const int bm = blockIdx.y * 128, bn = blockIdx.x * 128;

    ACC_INIT(acc);
    bf16_gemm_128x128(Qg + zoff + (size_t)bm * DIM, Kg + zoff + (size_t)bn * DIM,
                      sb, tid, acc);

    const int lane = tid & 31, wid = tid >> 5;
    const int wm = wid & 3, wn = wid >> 2;
    const int q = lane & 3, rg = lane >> 2;
    const float scale = 0.04419417382415922f;  // 1/sqrt(512)
#pragma unroll
    for (int mt = 0; mt < 2; mt++)
#pragma unroll
    for (int nt = 0; nt < 8; nt++) {
        const int rl0 = bm + wm * 32 + mt * 16 + rg;
        const int cl  = bn + wn * 64 + nt * 8 + 2 * q;
#pragma unroll
        for (int h = 0; h < 2; h++) {
            const int r = rl0 + h * 8;
            const size_t base = ((size_t)blockIdx.z * BL + r) * DIM + cl;
            float2 mv = *(const float2*)(mask + base);
            float v0 = acc[mt][nt][2 * h + 0] * scale + (1.f - mv.x) * (-1e10f);
            float v1 = acc[mt][nt][2 * h + 1] * scale + (1.f - mv.y) * (-1e10f);
            v0 = __expf(v0);
            v1 = __expf(v1);
            __nv_bfloat162 o = __float22bfloat162_rn(make_float2(v0, v1));
            *(__nv_bfloat162*)(Pg + base) = o;
        }
    }
}

// ---------------------------------------------------------------------------
// Output: out fp32 = (P@V)/rowsum(P) + X. P K-major (rowsum from A frags);
// V consumed NN via ldmatrix.trans. grid (4, 4, 64)
// ---------------------------------------------------------------------------
__global__ void __launch_bounds__(256, 2)
tc_gemm_out(const __nv_bfloat16* __restrict__ Pg, const __nv_bfloat16* __restrict__ Vg,
            const float* __restrict__ X, float* __restrict__ out)
{
    extern __shared__ uint32_t smu[];
    const uint32_t sb = smem_u32(smu);
    const int tid = threadIdx.x;
    const int lane = tid & 31, wid = tid >> 5;
    const int wm = wid & 3, wn = wid >> 2;
    const size_t zoff = (size_t)blockIdx.z * (BL * DIM);
    const int bm = blockIdx.y * 128, bn = blockIdx.x * 128;

    const __nv_bfloat16* A = Pg + zoff + (size_t)bm * DIM;
    const __nv_bfloat16* V = Vg + zoff;

    const int a_row = wm * 32 + (lane & 15);
    const int a_kb  = (lane >> 4) * 16;
    const uint32_t a_base = sb + (uint32_t)(a_row * AROW_B) + a_kb;
    const int g = lane >> 3;
    const uint32_t bt_off = (uint32_t)(((g & 1) * 8 + (lane & 7)) * VROW_B + ((g >> 1) * 8) * 2);

    ACC_INIT(acc);
    float rsum[2][2] = {{0.f, 0.f}, {0.f, 0.f}};

    auto load = [&](int c, int s) {
        const uint32_t as = sb + (uint32_t)s * A_STG;
        const uint32_t bs = sb + B_OFF + (uint32_t)s * V_STG;
#pragma unroll
        for (int t = 0; t < 2; t++) {
            int idx = tid + t * 256;
            int r = idx >> 2, c4 = idx & 3;
            CP16(as + (uint32_t)(r * AROW_B + c4 * 16),
                 A + (size_t)r * DIM + c * 32 + c4 * 8);
            int vr = idx >> 4, v16 = idx & 15;        // 32 rows x 16 chunks
            CP16(bs + (uint32_t)(vr * VROW_B + v16 * 16),
                 V + (size_t)(c * 32 + vr) * DIM + bn + v16 * 8);
        }
        CPCOMMIT();
    };

    load(0, 0); load(1, 1); load(2, 2); load(3, 3);
#pragma unroll 1
    for (int c = 0; c < NCHUNK; c++) {
        CPWAIT3();
        __syncthreads();
        if (c + 4 < NCHUNK) load(c + 4, (c + 4) % NSTAGE); else CPCOMMIT();
        const int s = c % NSTAGE;
        const uint32_t aaddr = a_base + (uint32_t)s * A_STG;
        const uint32_t baddr = sb + B_OFF + (uint32_t)s * V_STG + bt_off;
#pragma unroll
        for (int ks = 0; ks < 2; ks++) {
            uint32_t af[2][4], bf[4][4];
            LDSM4(af[0], aaddr + ks * 32);
            LDSM4(af[1], aaddr + ks * 32 + 16 * AROW_B);
#pragma unroll
            for (int gg = 0; gg < 4; gg++)
                LDSM4T(bf[gg], baddr + (uint32_t)(ks * 16 * VROW_B) +
                               (uint32_t)((wn * 64 + gg * 16) * 2));
#pragma unroll
            for (int mt = 0; mt < 2; mt++)
#pragma unroll
                for (int gg = 0; gg < 4; gg++) {
                    mma16(acc[mt][2 * gg + 0], af[mt], &bf[gg][0]);
                    mma16(acc[mt][2 * gg + 1], af[mt], &bf[gg][2]);
                }
#pragma unroll
            for (int mt = 0; mt < 2; mt++) {
                rsum[mt][0] += bf2sum(af[mt][0]) + bf2sum(af[mt][2]);
                rsum[mt][1] += bf2sum(af[mt][1]) + bf2sum(af[mt][3]);
            }
        }
    }
    CPWAIT0();
    __syncthreads();

    // reduce rowsum over the q lanes, stash per-row in smem (stages dead)
    float* rowsum_sm = (float*)smu;
#pragma unroll
    for (int mt = 0; mt < 2; mt++)
#pragma unroll
    for (int h = 0; h < 2; h++) {
        rsum[mt][h] += __shfl_xor_sync(0xFFFFFFFFu, rsum[mt][h], 1);
        rsum[mt][h] += __shfl_xor_sync(0xFFFFFFFFu, rsum[mt][h], 2);
    }
    const int q = lane & 3, rg = lane >> 2;
    if (wn == 0 && q == 0) {
#pragma unroll
        for (int mt = 0; mt < 2; mt++)
#pragma unroll
        for (int h = 0; h < 2; h++)
            rowsum_sm[wm * 32 + mt * 16 + rg + 8 * h] = rsum[mt][h];
    }
    __syncthreads();

#pragma unroll
    for (int mt = 0; mt < 2; mt++)
#pragma unroll
    for (int h = 0; h < 2; h++) {
        const int rl = wm * 32 + mt * 16 + rg + h * 8;
        const float inv = 1.f / rowsum_sm[rl];
        const int r = bm + rl;
#pragma unroll
        for (int nt = 0; nt < 8; nt++) {
            const int cl = bn + wn * 64 + nt * 8 + 2 * q;
            const size_t base = ((size_t)blockIdx.z * BL + r) * DIM + cl;
            float2 xv = *(const float2*)(X + base);
            *(float2*)(out + base) = make_float2(acc[mt][nt][2 * h + 0] * inv + xv.x,
                                                 acc[mt][nt][2 * h + 1] * inv + xv.y);
        }
    }
}

// ---------------------------------------------------------------------------
// fp32 -> bf16 elementwise (8 elems/thread)
// ---------------------------------------------------------------------------
__global__ __launch_bounds__(256)
void cvt_bf16(const float4* __restrict__ src, uint2* __restrict__ dst, int n8) {
    int i = blockIdx.x * 256 + threadIdx.x;
    if (i < n8) {
        float4 a = src[2 * i], b = src[2 * i + 1];
        uint2 o, o2;
        o.x = ((uint32_t)__bfloat16_as_ushort(__float2bfloat16(a.y)) << 16)
            |  (uint32_t)__bfloat16_as_ushort(__float2bfloat16(a.x));
        o.y = ((uint32_t)__bfloat16_as_ushort(__float2bfloat16(a.w)) << 16)
            |  (uint32_t)__bfloat16_as_ushort(__float2bfloat16(a.z));
        o2.x = ((uint32_t)__bfloat16_as_ushort(__float2bfloat16(b.y)) << 16)
             |  (uint32_t)__bfloat16_as_ushort(__float2bfloat16(b.x));
        o2.y = ((uint32_t)__bfloat16_as_ushort(__float2bfloat16(b.w)) << 16)
             |  (uint32_t)__bfloat16_as_ushort(__float2bfloat16(b.z));
        dst[2 * i] = o;
        dst[2 * i + 1] = o2;
    }
}

// ---------------------------------------------------------------------------
// Transpose + convert: W fp32 [512,512] -> Wt bf16 [n][k]; grid.z selects W
// ---------------------------------------------------------------------------
__global__ __launch_bounds__(256)
void wt_cvt(const float* __restrict__ w0, const float* __restrict__ w1,
            const float* __restrict__ w2, __nv_bfloat16* __restrict__ dst) {
    __shared__ float t[32][33];
    const int z = blockIdx.z;
    const float* src = (z == 0) ? w0 : (z == 1) ? w1 : w2;
    __nv_bfloat16* d = dst + (size_t)z * DIM * DIM;
    int x = blockIdx.x * 32 + threadIdx.x;
    int y = blockIdx.y * 32 + threadIdx.y;
#pragma unroll
    for (int j = 0; j < 32; j += 8)
        t[threadIdx.y + j][threadIdx.x] = src[(size_t)(y + j) * DIM + x];
    __syncthreads();
    x = blockIdx.y * 32 + threadIdx.x;
    y = blockIdx.x * 32 + threadIdx.y;
#pragma unroll
    for (int j = 0; j < 32; j += 8)
        d[(size_t)(y + j) * DIM + x] = __float2bfloat16(t[threadIdx.x][threadIdx.y + j]);
}

// ---------------------------------------------------------------------------
// LayerNorm rows in-place on d_out (eps=1e-3)
// ---------------------------------------------------------------------------
__global__ __launch_bounds__(128)
void ln_rows(float* __restrict__ out) {
    const size_t row = blockIdx.x;
    float4* p = (float4*)(out + row * DIM);
    const int tid = threadIdx.x;
    float4 v = p[tid];
    float s  = v.x + v.y + v.z + v.w;
    float sq = v.x*v.x + v.y*v.y + v.z*v.z + v.w*v.w;
#pragma unroll
    for (int o = 16; o; o >>= 1) {
        s  += __shfl_xor_sync(0xFFFFFFFFu, s,  o);
        sq += __shfl_xor_sync(0xFFFFFFFFu, sq, o);
    }
    __shared__ float ws[4], wq[4];
    if ((tid & 31) == 0) { ws[tid >> 5] = s; wq[tid >> 5] = sq; }
    __syncthreads();
    s  = ws[0] + ws[1] + ws[2] + ws[3];
    sq = wq[0] + wq[1] + wq[2] + wq[3];
    const float inv = 1.f / (float)DIM;
    float mean = s * inv;
    float var  = sq * inv - mean * mean;
    float r = rsqrtf(var + 1e-3f);
    v.x = (v.x - mean) * r; v.y = (v.y - mean) * r;
    v.z = (v.z - mean) * r; v.w = (v.w - mean) * r;
    p[tid] = v;
}

// ---------------------------------------------------------------------------
extern "C" void kernel_launch(void* const* d_in, const int* in_sizes, int n_in,
                              void* d_out, int out_size) {
    const float* X    = (const float*)d_in[0];
    const float* mask = (const float*)d_in[1];
    const float* dw1  = (const float*)d_in[2];
    const float* dw2  = (const float*)d_in[3];
    const float* dw3  = (const float*)d_in[4];
    const float* db1  = (const float*)d_in[5];
    const float* db2  = (const float*)d_in[6];
    const float* db3  = (const float*)d_in[7];
    float* out = (float*)d_out;

    __nv_bfloat16 *Xh, *Wth, *Qh, *Kh, *Vh, *Ph;
    cudaGetSymbolAddress((void**)&Xh,  g_Xh);
    cudaGetSymbolAddress((void**)&Wth, g_Wth);
    cudaGetSymbolAddress((void**)&Qh,  g_Qh);
    cudaGetSymbolAddress((void**)&Kh,  g_Kh);
    cudaGetSymbolAddress((void**)&Vh,  g_Vh);
    cudaGetSymbolAddress((void**)&Ph,  g_Ph);

    static int attr_done = 0;
    if (!attr_done) {
        cudaFuncSetAttribute(tc_gemm_qkv,    cudaFuncAttributeMaxDynamicSharedMemorySize, SMEM_BYTES);
        cudaFuncSetAttribute(tc_gemm_scores, cudaFuncAttributeMaxDynamicSharedMemorySize, SMEM_BYTES);
        cudaFuncSetAttribute(tc_gemm_out,    cudaFuncAttributeMaxDynamicSharedMemorySize, SMEM_BYTES);
        attr_done = 1;
    }

    cvt_bf16<<<(NROWS * DIM / 8 + 255) / 256, 256>>>((const float4*)X, (uint2*)Xh, NROWS * DIM / 8);
    dim3 tblk(32, 8);
    wt_cvt<<<dim3(16, 16, 3), tblk>>>(dw1, dw2, dw3, Wth);

    tc_gemm_qkv<<<dim3(4, 256, 3), 256, SMEM_BYTES>>>(Xh, Wth, db1, db2, db3, Qh, Kh, Vh);

    tc_gemm_scores<<<dim3(4, 4, NBLK), 256, SMEM_BYTES>>>(Qh, Kh, mask, Ph);

    tc_gemm_out<<<dim3(4, 4, NBLK), 256, SMEM_BYTES>>>(Ph, Vh, X, out);

    ln_rows<<<NROWS, 128>>>(out);
}

// round 11
// speedup vs baseline: 1.2557x; 1.2557x over previous
#include <cuda_runtime.h>
#include <cuda.h>
#include <cuda_bf16.h>
#include <cstdint>
#include <math.h>

#define BL 512
#define DIM 512
#define NROWS 32768
#define NBLK 64

// Scratch (allocation-free rule: __device__ globals)
__device__ __nv_bfloat16 g_Xh [(size_t)NROWS*DIM];
__device__ __nv_bfloat16 g_Wth[(size_t)3*DIM*DIM];
__device__ __nv_bfloat16 g_Qh [(size_t)NROWS*DIM];
__device__ __nv_bfloat16 g_Kh [(size_t)NROWS*DIM];
__device__ __nv_bfloat16 g_Vh [(size_t)NROWS*DIM];
__device__ __nv_bfloat16 g_Ph [(size_t)NBLK*BL*BL];   // unnormalized exp(S), bf16

// ---------------------------------------------------------------------------
__device__ __forceinline__ uint32_t smem_u32(const void* p) {
    uint32_t a;
    asm("{ .reg .u64 t; cvta.to.shared.u64 t, %1; cvt.u32.u64 %0, t; }" : "=r"(a) : "l"(p));
    return a;
}
#define MBARRIER_INIT(addr, cnt) \
    asm volatile("mbarrier.init.shared.b64 [%0], %1;" :: "r"((uint32_t)(addr)), "r"((uint32_t)(cnt)) : "memory")
#define MBARRIER_EXPECT_TX(addr, bytes) \
    asm volatile("mbarrier.arrive.expect_tx.shared.b64 _, [%0], %1;" \
                 :: "r"((uint32_t)(addr)), "r"((uint32_t)(bytes)) : "memory")
#define MBARRIER_WAIT_PARITY(addr, par) do {                                   \
    uint32_t _m = (uint32_t)(addr); uint32_t _p = (uint32_t)(par); uint32_t _d;\
    asm volatile("{\n\t.reg .pred p;\n\t"                                      \
        "mbarrier.try_wait.parity.acquire.cta.shared::cta.b64 p, [%1], %2;\n\t"\
        "selp.b32 %0, 1, 0, p;\n\t}" : "=r"(_d) : "r"(_m), "r"(_p) : "memory");\
    if (!_d) {                                                                 \
        asm volatile("{\n\t.reg .pred P1;\n\t"                                 \
        "W_%=:\n\t"                                                            \
        "mbarrier.try_wait.parity.acquire.cta.shared::cta.b64 P1, [%0], %1, 0x989680;\n\t" \
        "@P1 bra.uni D_%=;\n\tbra.uni W_%=;\n\tD_%=:\n\t}"                     \
        :: "r"(_m), "r"(_p) : "memory");                                       \
    }                                                                          \
} while (0)
#define TMA_LOAD2D(saddr, tmap, cx, cy, mbar) \
    asm volatile("cp.async.bulk.tensor.2d.shared::cta.global.tile.mbarrier::complete_tx::bytes " \
        "[%0], [%1, {%2, %3}], [%4];" \
        :: "r"((uint32_t)(saddr)), "l"(tmap), "r"((int)(cx)), "r"((int)(cy)), \
           "r"((uint32_t)(mbar)) : "memory")
#define LDSM4(R, addr) \
    asm volatile("ldmatrix.sync.aligned.m8n8.x4.shared.b16 {%0,%1,%2,%3}, [%4];" \
        : "=r"((R)[0]), "=r"((R)[1]), "=r"((R)[2]), "=r"((R)[3]) : "r"(addr))
#define LDSM4T(R, addr) \
    asm volatile("ldmatrix.sync.aligned.m8n8.x4.trans.shared.b16 {%0,%1,%2,%3}, [%4];" \
        : "=r"((R)[0]), "=r"((R)[1]), "=r"((R)[2]), "=r"((R)[3]) : "r"(addr))

__device__ __forceinline__ void mma16(float* c, const uint32_t* a, const uint32_t* b) {
    asm volatile(
        "mma.sync.aligned.m16n8k16.row.col.f32.bf16.bf16.f32 "
        "{%0,%1,%2,%3},{%4,%5,%6,%7},{%8,%9},{%0,%1,%2,%3};"
        : "+f"(c[0]), "+f"(c[1]), "+f"(c[2]), "+f"(c[3])
        : "r"(a[0]), "r"(a[1]), "r"(a[2]), "r"(a[3]),
          "r"(b[0]), "r"(b[1]));
}
__device__ __forceinline__ float bf2sum(uint32_t u) {
    __nv_bfloat162 h = *(__nv_bfloat162*)&u;
    float2 f = __bfloat1622float2(h);
    return f.x + f.y;
}

// ---------------------------------------------------------------------------
// TMA double-buffered GEMM. Stage = 128 rows x 128 B (SW128), 16 KB/operand.
// smem: [A stages 2x16K][B stages 2x16K][mbarriers]. Chunk = 64 K-elements.
// ---------------------------------------------------------------------------
#define STG_B       16384
#define BARS_OFF    65536
#define SMEM_BYTES  (65536 + 64 + 1024)   /* + alignment slack */

#define ACC_INIT(acc)                                         \
    float acc[2][8][4];                                       \
    _Pragma("unroll") for (int i = 0; i < 2; i++)             \
    _Pragma("unroll") for (int j = 0; j < 8; j++)             \
    _Pragma("unroll") for (int k = 0; k < 4; k++) acc[i][j][k] = 0.f;

// NT mainloop: acc = A[128x512] @ B[128x512]^T, both K-major via TMA maps
__device__ __forceinline__ void tma_gemm_nt(
    const CUtensorMap* mA, const CUtensorMap* mB, int rowA0, int rowB0,
    uint32_t sb, int tid, float acc[2][8][4])
{
    const uint32_t bars = sb + BARS_OFF;
    if (tid == 0) { MBARRIER_INIT(bars, 1); MBARRIER_INIT(bars + 8, 1); }
    __syncthreads();

    const int lane = tid & 31, wid = tid >> 5;
    const int wm = wid & 3, wn = wid >> 2;
    const int a_row = wm * 32 + (lane & 15);
    const uint32_t abase = (uint32_t)(a_row * 128 + (lane >> 4) * 16);
    const uint32_t axor  = (uint32_t)((a_row & 7) << 4);
    const int b_row = wn * 64 + ((lane >> 4) << 3) + (lane & 7);
    const uint32_t bbase = (uint32_t)(b_row * 128 + ((lane >> 3) & 1) * 16);
    const uint32_t bxor  = (uint32_t)((b_row & 7) << 4);

    auto issue = [&](int c, int s) {
        const uint32_t bar = bars + (uint32_t)s * 8;
        MBARRIER_EXPECT_TX(bar, 32768);
        TMA_LOAD2D(sb + (uint32_t)s * STG_B,             mA, c * 64, rowA0, bar);
        TMA_LOAD2D(sb + 32768 + (uint32_t)s * STG_B,     mB, c * 64, rowB0, bar);
    };
    if (tid == 0) { issue(0, 0); issue(1, 1); }

    int ph0 = 0, ph1 = 0;
#pragma unroll 1
    for (int c = 0; c < 8; c++) {
        const int s = c & 1;
        if (s == 0) { MBARRIER_WAIT_PARITY(bars,     ph0); ph0 ^= 1; }
        else        { MBARRIER_WAIT_PARITY(bars + 8, ph1); ph1 ^= 1; }
        const uint32_t as = sb + (uint32_t)s * STG_B;
        const uint32_t bs = sb + 32768 + (uint32_t)s * STG_B;
#pragma unroll
        for (int ks = 0; ks < 4; ks++) {
            uint32_t af[2][4], bf[4][4];
            const uint32_t a0 = as + ((abase + ks * 32) ^ axor);
            LDSM4(af[0], a0);
            LDSM4(af[1], a0 + 2048);
            const uint32_t b0 = bs + ((bbase + ks * 32) ^ bxor);
#pragma unroll
            for (int gg = 0; gg < 4; gg++)
                LDSM4(bf[gg], b0 + (uint32_t)gg * 2048);
#pragma unroll
            for (int mt = 0; mt < 2; mt++)
#pragma unroll
                for (int gg = 0; gg < 4; gg++) {
                    mma16(acc[mt][2 * gg + 0], af[mt], &bf[gg][0]);
                    mma16(acc[mt][2 * gg + 1], af[mt], &bf[gg][2]);
                }
        }
        __syncthreads();
        if (tid == 0 && c + 2 < 8) issue(c + 2, s);
    }
}

// ---------------------------------------------------------------------------
// QKV: grid (4, 256, 3). C bf16 = X@Wt^T + bias
// ---------------------------------------------------------------------------
__global__ void __launch_bounds__(256, 2)
tc_gemm_qkv(const __grid_constant__ CUtensorMap mX, const __grid_constant__ CUtensorMap mW,
            const float* __restrict__ b0, const float* __restrict__ b1,
            const float* __restrict__ b2,
            __nv_bfloat16* __restrict__ Qh, __nv_bfloat16* __restrict__ Kh,
            __nv_bfloat16* __restrict__ Vh)
{
    extern __shared__ char smc[];
    const uint32_t sb = (smem_u32(smc) + 1023u) & ~1023u;
    const int tid = threadIdx.x;
    const int z = blockIdx.z;
    const int bm = blockIdx.y * 128, bn = blockIdx.x * 128;

    const float* bias = (z == 0) ? b0 : (z == 1) ? b1 : b2;
    __nv_bfloat16* C = (z == 0) ? Qh : (z == 1) ? Kh : Vh;

    ACC_INIT(acc);
    tma_gemm_nt(&mX, &mW, bm, z * 512 + bn, sb, tid, acc);

    const int lane = tid & 31, wid = tid >> 5;
    const int wm = wid & 3, wn = wid >> 2;
    const int q = lane & 3, rg = lane >> 2;
#pragma unroll
    for (int mt = 0; mt < 2; mt++)
#pragma unroll
    for (int nt = 0; nt < 8; nt++) {
        const int rl0 = bm + wm * 32 + mt * 16 + rg;
        const int cl  = bn + wn * 64 + nt * 8 + 2 * q;
        float2 bv = *(const float2*)(bias + cl);
#pragma unroll
        for (int h = 0; h < 2; h++) {
            const int r = rl0 + h * 8;
            float v0 = acc[mt][nt][2 * h + 0] + bv.x;
            float v1 = acc[mt][nt][2 * h + 1] + bv.y;
            __nv_bfloat162 o = __float22bfloat162_rn(make_float2(v0, v1));
            *(__nv_bfloat162*)(C + (size_t)r * DIM + cl) = o;
        }
    }
}

// ---------------------------------------------------------------------------
// Scores+exp: P bf16 = exp(scale*(Q@K^T) + (1-mask)*(-1e10))   grid (4,4,64)
// ---------------------------------------------------------------------------
__global__ void __launch_bounds__(256, 2)
tc_gemm_scores(const __grid_constant__ CUtensorMap mQ, const __grid_constant__ CUtensorMap mK,
               const float* __restrict__ mask, __nv_bfloat16* __restrict__ Pg)
{
    extern __shared__ char smc[];
    const uint32_t sb = (smem_u32(smc) + 1023u) & ~1023u;
    const int tid = threadIdx.x;
    const int z = blockIdx.z;
    const int bm = blockIdx.y * 128, bn = blockIdx.x * 128;

    ACC_INIT(acc);
    tma_gemm_nt(&mQ, &mK, z * 512 + bm, z * 512 + bn, sb, tid, acc);

    const int lane = tid & 31, wid = tid >> 5;
    const int wm = wid & 3, wn = wid >> 2;
    const int q = lane & 3, rg = lane >> 2;
    const float scale = 0.04419417382415922f;  // 1/sqrt(512)
#pragma unroll
    for (int mt = 0; mt < 2; mt++)
#pragma unroll
    for (int nt = 0; nt < 8; nt++) {
        const int rl0 = bm + wm * 32 + mt * 16 + rg;
        const int cl  = bn + wn * 64 + nt * 8 + 2 * q;
#pragma unroll
        for (int h = 0; h < 2; h++) {
            const int r = rl0 + h * 8;
            const size_t base = ((size_t)z * BL + r) * DIM + cl;
            float2 mv = *(const float2*)(mask + base);
            float v0 = acc[mt][nt][2 * h + 0] * scale + (1.f - mv.x) * (-1e10f);
            float v1 = acc[mt][nt][2 * h + 1] * scale + (1.f - mv.y) * (-1e10f);
            v0 = __expf(v0);
            v1 = __expf(v1);
            __nv_bfloat162 o = __float22bfloat162_rn(make_float2(v0, v1));
            *(__nv_bfloat162*)(Pg + base) = o;
        }
    }
}

// ---------------------------------------------------------------------------
// Output: out fp32 = (P@V)/rowsum(P) + X. P K-major (rowsum from A frags);
// V loaded NN in two 64-col TMA boxes, consumed via ldmatrix.trans.
// grid (4, 4, 64)
// ---------------------------------------------------------------------------
__global__ void __launch_bounds__(256, 2)
tc_gemm_out(const __grid_constant__ CUtensorMap mP, const __grid_constant__ CUtensorMap mV,
            const float* __restrict__ X, float* __restrict__ out)
{
    extern __shared__ char smc[];
    const uint32_t sb = (smem_u32(smc) + 1023u) & ~1023u;
    const int tid = threadIdx.x;
    const int lane = tid & 31, wid = tid >> 5;
    const int wm = wid & 3, wn = wid >> 2;
    const int z = blockIdx.z;
    const int bm = blockIdx.y * 128, bn = blockIdx.x * 128;

    const uint32_t bars = sb + BARS_OFF;
    if (tid == 0) { MBARRIER_INIT(bars, 1); MBARRIER_INIT(bars + 8, 1); }
    __syncthreads();

    const int a_row = wm * 32 + (lane & 15);
    const uint32_t abase = (uint32_t)(a_row * 128 + (lane >> 4) * 16);
    const uint32_t axor  = (uint32_t)((a_row & 7) << 4);
    const int g = lane >> 3;
    const int v_rowb = (g & 1) * 8 + (lane & 7);
    const uint32_t vcolb = (uint32_t)((g >> 1) * 16);
    const uint32_t vxor  = (uint32_t)((v_rowb & 7) << 4);
    const uint32_t vreg  = (uint32_t)wn * 8192;   // warp's 64-col region

    auto issue = [&](int c, int s) {
        const uint32_t bar = bars + (uint32_t)s * 8;
        const uint32_t vs = sb + 32768 + (uint32_t)s * STG_B;
        MBARRIER_EXPECT_TX(bar, 32768);
        TMA_LOAD2D(sb + (uint32_t)s * STG_B, &mP, c * 64, z * 512 + bm, bar);
        TMA_LOAD2D(vs,        &mV, bn,      z * 512 + c * 64, bar);
        TMA_LOAD2D(vs + 8192, &mV, bn + 64, z * 512 + c * 64, bar);
    };
    if (tid == 0) { issue(0, 0); issue(1, 1); }

    ACC_INIT(acc);
    float rsum[2][2] = {{0.f, 0.f}, {0.f, 0.f}};

    int ph0 = 0, ph1 = 0;
#pragma unroll 1
    for (int c = 0; c < 8; c++) {
        const int s = c & 1;
        if (s == 0) { MBARRIER_WAIT_PARITY(bars,     ph0); ph0 ^= 1; }
        else        { MBARRIER_WAIT_PARITY(bars + 8, ph1); ph1 ^= 1; }
        const uint32_t as = sb + (uint32_t)s * STG_B;
        const uint32_t vs = sb + 32768 + (uint32_t)s * STG_B + vreg;
#pragma unroll
        for (int ks = 0; ks < 4; ks++) {
            uint32_t af[2][4], bf[4][4];
            const uint32_t a0 = as + ((abase + ks * 32) ^ axor);
            LDSM4(af[0], a0);
            LDSM4(af[1], a0 + 2048);
#pragma unroll
            for (int gg = 0; gg < 4; gg++) {
                const uint32_t off = (uint32_t)(v_rowb * 128 + ks * 2048 + gg * 32) + vcolb;
                LDSM4T(bf[gg], vs + (off ^ vxor));
            }
#pragma unroll
            for (int mt = 0; mt < 2; mt++)
#pragma unroll
                for (int gg = 0; gg < 4; gg++) {
                    mma16(acc[mt][2 * gg + 0], af[mt], &bf[gg][0]);
                    mma16(acc[mt][2 * gg + 1], af[mt], &bf[gg][2]);
                }
#pragma unroll
            for (int mt = 0; mt < 2; mt++) {
                rsum[mt][0] += bf2sum(af[mt][0]) + bf2sum(af[mt][2]);
                rsum[mt][1] += bf2sum(af[mt][1]) + bf2sum(af[mt][3]);
            }
        }
        __syncthreads();
        if (tid == 0 && c + 2 < 8) issue(c + 2, s);
    }

    // reduce rowsum over the q lanes, stash per-row in smem (stages dead)
    float* rowsum_sm = (float*)smc;
#pragma unroll
    for (int mt = 0; mt < 2; mt++)
#pragma unroll
    for (int h = 0; h < 2; h++) {
        rsum[mt][h] += __shfl_xor_sync(0xFFFFFFFFu, rsum[mt][h], 1);
        rsum[mt][h] += __shfl_xor_sync(0xFFFFFFFFu, rsum[mt][h], 2);
    }
    const int q = lane & 3, rg = lane >> 2;
    if (wn == 0 && q == 0) {
#pragma unroll
        for (int mt = 0; mt < 2; mt++)
#pragma unroll
        for (int h = 0; h < 2; h++)
            rowsum_sm[wm * 32 + mt * 16 + rg + 8 * h] = rsum[mt][h];
    }
    __syncthreads();

#pragma unroll
    for (int mt = 0; mt < 2; mt++)
#pragma unroll
    for (int h = 0; h < 2; h++) {
        const int rl = wm * 32 + mt * 16 + rg + h * 8;
        const float inv = 1.f / rowsum_sm[rl];
        const int r = bm + rl;
#pragma unroll
        for (int nt = 0; nt < 8; nt++) {
            const int cl = bn + wn * 64 + nt * 8 + 2 * q;
            const size_t base = ((size_t)z * BL + r) * DIM + cl;
            float2 xv = *(const float2*)(X + base);
            *(float2*)(out + base) = make_float2(acc[mt][nt][2 * h + 0] * inv + xv.x,
                                                 acc[mt][nt][2 * h + 1] * inv + xv.y);
        }
    }
}

// ---------------------------------------------------------------------------
// fp32 -> bf16 elementwise (8 elems/thread)
// ---------------------------------------------------------------------------
__global__ __launch_bounds__(256)
void cvt_bf16(const float4* __restrict__ src, uint2* __restrict__ dst, int n8) {
    int i = blockIdx.x * 256 + threadIdx.x;
    if (i < n8) {
        float4 a = src[2 * i], b = src[2 * i + 1];
        uint2 o, o2;
        o.x = ((uint32_t)__bfloat16_as_ushort(__float2bfloat16(a.y)) << 16)
            |  (uint32_t)__bfloat16_as_ushort(__float2bfloat16(a.x));
        o.y = ((uint32_t)__bfloat16_as_ushort(__float2bfloat16(a.w)) << 16)
            |  (uint32_t)__bfloat16_as_ushort(__float2bfloat16(a.z));
        o2.x = ((uint32_t)__bfloat16_as_ushort(__float2bfloat16(b.y)) << 16)
             |  (uint32_t)__bfloat16_as_ushort(__float2bfloat16(b.x));
        o2.y = ((uint32_t)__bfloat16_as_ushort(__float2bfloat16(b.w)) << 16)
             |  (uint32_t)__bfloat16_as_ushort(__float2bfloat16(b.z));
        dst[2 * i] = o;
        dst[2 * i + 1] = o2;
    }
}

// ---------------------------------------------------------------------------
// Transpose + convert: W fp32 [512,512] -> Wt bf16 [n][k]; grid.z selects W
// ---------------------------------------------------------------------------
__global__ __launch_bounds__(256)
void wt_cvt(const float* __restrict__ w0, const float* __restrict__ w1,
            const float* __restrict__ w2, __nv_bfloat16* __restrict__ dst) {
    __shared__ float t[32][33];
    const int z = blockIdx.z;
    const float* src = (z == 0) ? w0 : (z == 1) ? w1 : w2;
    __nv_bfloat16* d = dst + (size_t)z * DIM * DIM;
    int x = blockIdx.x * 32 + threadIdx.x;
    int y = blockIdx.y * 32 + threadIdx.y;
#pragma unroll
    for (int j = 0; j < 32; j += 8)
        t[threadIdx.y + j][threadIdx.x] = src[(size_t)(y + j) * DIM + x];
    __syncthreads();
    x = blockIdx.y * 32 + threadIdx.x;
    y = blockIdx.x * 32 + threadIdx.y;
#pragma unroll
    for (int j = 0; j < 32; j += 8)
        d[(size_t)(y + j) * DIM + x] = __float2bfloat16(t[threadIdx.x][threadIdx.y + j]);
}

// ---------------------------------------------------------------------------
// LayerNorm rows in-place on d_out (eps=1e-3)
// ---------------------------------------------------------------------------
__global__ __launch_bounds__(128)
void ln_rows(float* __restrict__ out) {
    const size_t row = blockIdx.x;
    float4* p = (float4*)(out + row * DIM);
    const int tid = threadIdx.x;
    float4 v = p[tid];
    float s  = v.x + v.y + v.z + v.w;
    float sq = v.x*v.x + v.y*v.y + v.z*v.z + v.w*v.w;
#pragma unroll
    for (int o = 16; o; o >>= 1) {
        s  += __shfl_xor_sync(0xFFFFFFFFu, s,  o);
        sq += __shfl_xor_sync(0xFFFFFFFFu, sq, o);
    }
    __shared__ float ws[4], wq[4];
    if ((tid & 31) == 0) { ws[tid >> 5] = s; wq[tid >> 5] = sq; }
    __syncthreads();
    s  = ws[0] + ws[1] + ws[2] + ws[3];
    sq = wq[0] + wq[1] + wq[2] + wq[3];
    const float inv = 1.f / (float)DIM;
    float mean = s * inv;
    float var  = sq * inv - mean * mean;
    float r = rsqrtf(var + 1e-3f);
    v.x = (v.x - mean) * r; v.y = (v.y - mean) * r;
    v.z = (v.z - mean) * r; v.w = (v.w - mean) * r;
    p[tid] = v;
}

// ---------------------------------------------------------------------------
// Host: tensor-map creation via driver entry point (no -lcuda needed)
// ---------------------------------------------------------------------------
typedef CUresult (*PFN_tmencode)(
    CUtensorMap*, CUtensorMapDataType, cuuint32_t, void*,
    const cuuint64_t*, const cuuint64_t*, const cuuint32_t*, const cuuint32_t*,
    CUtensorMapInterleave, CUtensorMapSwizzle, CUtensorMapL2promotion,
    CUtensorMapFloatOOBfill);

static PFN_tmencode get_encoder() {
    static PFN_tmencode fn = nullptr;
    if (!fn) {
        void* p = nullptr;
        cudaDriverEntryPointQueryResult qr;
        cudaGetDriverEntryPointByVersion("cuTensorMapEncodeTiled", &p, 12000,
                                         cudaEnableDefault, &qr);
        fn = (PFN_tmencode)p;
    }
    return fn;
}

static void make_map(CUtensorMap* m, void* base, unsigned long long rows,
                     unsigned bx, unsigned by) {
    cuuint64_t dims[2]    = {512ull, rows};
    cuuint64_t strides[1] = {1024ull};          // bytes per row
    cuuint32_t box[2]     = {bx, by};
    cuuint32_t es[2]      = {1u, 1u};
    get_encoder()(m, CU_TENSOR_MAP_DATA_TYPE_BFLOAT16, 2, base,
                  dims, strides, box, es,
                  CU_TENSOR_MAP_INTERLEAVE_NONE, CU_TENSOR_MAP_SWIZZLE_128B,
                  CU_TENSOR_MAP_L2_PROMOTION_L2_128B,
                  CU_TENSOR_MAP_FLOAT_OOB_FILL_NONE);
}

// ---------------------------------------------------------------------------
extern "C" void kernel_launch(void* const* d_in, const int* in_sizes, int n_in,
                              void* d_out, int out_size) {
    const float* X    = (const float*)d_in[0];
    const float* mask = (const float*)d_in[1];
    const float* dw1  = (const float*)d_in[2];
    const float* dw2  = (const float*)d_in[3];
    const float* dw3  = (const float*)d_in[4];
    const float* db1  = (const float*)d_in[5];
    const float* db2  = (const float*)d_in[6];
    const float* db3  = (const float*)d_in[7];
    float* out = (float*)d_out;

    __nv_bfloat16 *Xh, *Wth, *Qh, *Kh, *Vh, *Ph;
    cudaGetSymbolAddress((void**)&Xh,  g_Xh);
    cudaGetSymbolAddress((void**)&Wth, g_Wth);
    cudaGetSymbolAddress((void**)&Qh,  g_Qh);
    cudaGetSymbolAddress((void**)&Kh,  g_Kh);
    cudaGetSymbolAddress((void**)&Vh,  g_Vh);
    cudaGetSymbolAddress((void**)&Ph,  g_Ph);

    static int attr_done = 0;
    if (!attr_done) {
        cudaFuncSetAttribute(tc_gemm_qkv,    cudaFuncAttributeMaxDynamicSharedMemorySize, SMEM_BYTES);
        cudaFuncSetAttribute(tc_gemm_scores, cudaFuncAttributeMaxDynamicSharedMemorySize, SMEM_BYTES);
        cudaFuncSetAttribute(tc_gemm_out,    cudaFuncAttributeMaxDynamicSharedMemorySize, SMEM_BYTES);
        attr_done = 1;
    }

    CUtensorMap mX, mW, mQ, mK, mP, mV;
    make_map(&mX, Xh,  32768ull, 64, 128);
    make_map(&mW, Wth, 1536ull,  64, 128);
    make_map(&mQ, Qh,  32768ull, 64, 128);
    make_map(&mK, Kh,  32768ull, 64, 128);
    make_map(&mP, Ph,  32768ull, 64, 128);
    make_map(&mV, Vh,  32768ull, 64, 64);

    cvt_bf16<<<(NROWS * DIM / 8 + 255) / 256, 256>>>((const float4*)X, (uint2*)Xh, NROWS * DIM / 8);
    dim3 tblk(32, 8);
    wt_cvt<<<dim3(16, 16, 3), tblk>>>(dw1, dw2, dw3, Wth);

    tc_gemm_qkv<<<dim3(4, 256, 3), 256, SMEM_BYTES>>>(mX, mW, db1, db2, db3, Qh, Kh, Vh);

    tc_gemm_scores<<<dim3(4, 4, NBLK), 256, SMEM_BYTES>>>(mQ, mK, mask, Ph);

    tc_gemm_out<<<dim3(4, 4, NBLK), 256, SMEM_BYTES>>>(mP, mV, X, out);

    ln_rows<<<NROWS, 128>>>(out);
}